// round 16
// baseline (speedup 1.0000x reference)
#include <cuda_runtime.h>
#include <cuda_bf16.h>

#define N_ROWS 8192
#define F_DIM  512
#define H1_DIM 512
#define SU_DIM 256
#define T_STEPS 16
#define BETA_F 0.95f
#define THR_F  1.0f

typedef unsigned int u32;
typedef unsigned long long u64;
typedef unsigned short u16;

// packed fp32x2 helpers (Blackwell native)
__device__ __forceinline__ u64 ffma2(u64 a, u64 b, u64 c) {
    u64 d;
    asm("fma.rn.f32x2 %0, %1, %2, %3;" : "=l"(d) : "l"(a), "l"(b), "l"(c));
    return d;
}
__device__ __forceinline__ u64 pack2(float x) {
    u64 d;
    asm("mov.b64 %0, {%1, %1};" : "=l"(d) : "f"(x));
    return d;
}
__device__ __forceinline__ float2 unpack2(u64 d) {
    float2 r;
    asm("mov.b64 {%0, %1}, %2;" : "=f"(r.x), "=f"(r.y) : "l"(d));
    return r;
}

// bf16 mma: D(16x8) += A(16x16) * B(16x8), fp32 accum
__device__ __forceinline__ void mma_bf16(float (&d)[4], u32 a0, u32 a1, u32 a2, u32 a3,
                                         u32 b0, u32 b1) {
    asm("mma.sync.aligned.m16n8k16.row.col.f32.bf16.bf16.f32 "
        "{%0,%1,%2,%3}, {%4,%5,%6,%7}, {%8,%9}, {%0,%1,%2,%3};"
        : "+f"(d[0]), "+f"(d[1]), "+f"(d[2]), "+f"(d[3])
        : "r"(a0), "r"(a1), "r"(a2), "r"(a3), "r"(b0), "r"(b1));
}

// ---------------- scratch (static device globals; no allocations) ----------------
__device__ unsigned g_spk1[N_ROWS * T_STEPS * (H1_DIM / 32)];  // 8 MB
__device__ __align__(16) u32 g_sfb16[N_ROWS * SU_DIM / 2];     // bf16 cnt pairs
__device__ float g_W2T[H1_DIM * SU_DIM];                       // [j][i]
__device__ __align__(16) u32 g_Wstg[16 * 8192];                // k_final staged W
__device__ float g_beff[F_DIM];

// ---------------- fused prep ----------------
__global__ __launch_bounds__(256) void k_prep(const float* __restrict__ W2,
                                              const float* __restrict__ Wfu,
                                              const float* __restrict__ Wf,
                                              const float* __restrict__ bf,
                                              const float* __restrict__ bfu) {
    int bid = blockIdx.x;
    if (bid < 512) {
        __shared__ float wrow[256];
        int f = bid;
        int i = threadIdx.x;
        wrow[i] = Wfu[f * 512 + i];
        __syncthreads();
        float acc = Wfu[f * 512 + 256 + i];
#pragma unroll 4
        for (int l = 0; l < 256; l++)
            acc = fmaf(wrow[l], Wf[l * 256 + i], acc);
        float w = acc * (1.f / 16.f);
        __nv_bfloat16 h = __float2bfloat16(w);
        float hf = __bfloat162float(h);
        __nv_bfloat16 lo = __float2bfloat16(w - hf);
        u16* ws = (u16*)g_Wstg;
        int kc = i >> 4, r = i & 15;
        ws[kc * 16384 + f * 16 + r]        = __bfloat16_as_ushort(h);
        ws[kc * 16384 + 8192 + f * 16 + r] = __bfloat16_as_ushort(lo);
    } else if (bid < 1024) {
        int idx = (bid - 512) * 256 + threadIdx.x;
        int i = idx >> 9;
        int j = idx & 511;
        g_W2T[j * SU_DIM + i] = W2[idx];
    } else {
#pragma unroll
        for (int p = 0; p < 2; p++) {
            int f = threadIdx.x + p * 256;
            float acc = bfu[f];
#pragma unroll 4
            for (int l = 0; l < 256; l++)
                acc = fmaf(Wfu[f * 512 + l], bf[l], acc);
            g_beff[f] = acc;
        }
    }
}

// ---------------- K1: cur0 = X @ W1^T + b1, FUSED spike recurrence, f32x2 ----------
#define K1_BM 128
#define K1_BN 128
#define K1_BK 16
#define K1_LDS 136

__global__ __launch_bounds__(256, 2) void k_gemm1(const float* __restrict__ X,
                                                  const float* __restrict__ W1,
                                                  const float* __restrict__ b1) {
    __shared__ __align__(16) unsigned char sm[128 * 16 * 16];
    float (*As)[K1_LDS] = (float (*)[K1_LDS])sm;
    float (*Bs)[K1_LDS] = (float (*)[K1_LDS])(sm + K1_BK * K1_LDS * 4);
    unsigned char (*pk)[16][16] = (unsigned char (*)[16][16])sm;

    const int n0 = blockIdx.y * K1_BM;
    const int h0 = blockIdx.x * K1_BN;
    const int tid = threadIdx.x;
    const int ty = tid >> 4;
    const int tx = tid & 15;

    const int lrow0 = tid >> 2;
    const int lkq0  = tid & 3;
    const int lrow1 = (tid + 256) >> 2;
    const int lkq1  = (tid + 256) & 3;

    float4 pa0, pa1, pb0, pb1;
    {
        pa0 = *(const float4*)(X  + (size_t)(n0 + lrow0) * 512 + lkq0 * 4);
        pb0 = *(const float4*)(W1 + (size_t)(h0 + lrow0) * 512 + lkq0 * 4);
        pa1 = *(const float4*)(X  + (size_t)(n0 + lrow1) * 512 + lkq1 * 4);
        pb1 = *(const float4*)(W1 + (size_t)(h0 + lrow1) * 512 + lkq1 * 4);
    }

    u64 accp[8][4];
#pragma unroll
    for (int i = 0; i < 8; i++)
#pragma unroll
        for (int jp = 0; jp < 4; jp++) accp[i][jp] = 0ull;

    for (int k0 = 0; k0 < 512; k0 += K1_BK) {
        As[lkq0 * 4 + 0][lrow0] = pa0.x;
        As[lkq0 * 4 + 1][lrow0] = pa0.y;
        As[lkq0 * 4 + 2][lrow0] = pa0.z;
        As[lkq0 * 4 + 3][lrow0] = pa0.w;
        Bs[lkq0 * 4 + 0][lrow0] = pb0.x;
        Bs[lkq0 * 4 + 1][lrow0] = pb0.y;
        Bs[lkq0 * 4 + 2][lrow0] = pb0.z;
        Bs[lkq0 * 4 + 3][lrow0] = pb0.w;
        As[lkq1 * 4 + 0][lrow1] = pa1.x;
        As[lkq1 * 4 + 1][lrow1] = pa1.y;
        As[lkq1 * 4 + 2][lrow1] = pa1.z;
        As[lkq1 * 4 + 3][lrow1] = pa1.w;
        Bs[lkq1 * 4 + 0][lrow1] = pb1.x;
        Bs[lkq1 * 4 + 1][lrow1] = pb1.y;
        Bs[lkq1 * 4 + 2][lrow1] = pb1.z;
        Bs[lkq1 * 4 + 3][lrow1] = pb1.w;
        __syncthreads();

        if (k0 + K1_BK < 512) {
            int kn = k0 + K1_BK;
            pa0 = *(const float4*)(X  + (size_t)(n0 + lrow0) * 512 + kn + lkq0 * 4);
            pb0 = *(const float4*)(W1 + (size_t)(h0 + lrow0) * 512 + kn + lkq0 * 4);
            pa1 = *(const float4*)(X  + (size_t)(n0 + lrow1) * 512 + kn + lkq1 * 4);
            pb1 = *(const float4*)(W1 + (size_t)(h0 + lrow1) * 512 + kn + lkq1 * 4);
        }

#pragma unroll
        for (int k = 0; k < K1_BK; k++) {
            float a[8];
            *(float4*)(a)     = *(const float4*)&As[k][ty * 8];
            *(float4*)(a + 4) = *(const float4*)&As[k][ty * 8 + 4];
            ulonglong2 t0 = *(const ulonglong2*)&Bs[k][tx * 8];
            ulonglong2 t1 = *(const ulonglong2*)&Bs[k][tx * 8 + 4];
            u64 b2[4] = {t0.x, t0.y, t1.x, t1.y};
#pragma unroll
            for (int i = 0; i < 8; i++) {
                u64 a2 = pack2(a[i]);
#pragma unroll
                for (int jp = 0; jp < 4; jp++)
                    accp[i][jp] = ffma2(a2, b2[jp], accp[i][jp]);
            }
        }
        __syncthreads();
    }

    float bv[8];
#pragma unroll
    for (int j = 0; j < 8; j++) bv[j] = b1[h0 + tx * 8 + j];

#pragma unroll
    for (int i = 0; i < 8; i++) {
        unsigned pw[4] = {0u, 0u, 0u, 0u};
#pragma unroll
        for (int jp = 0; jp < 4; jp++) {
            float2 u = unpack2(accp[i][jp]);
#pragma unroll
            for (int h = 0; h < 2; h++) {
                int j = jp * 2 + h;
                float c0 = (h ? u.y : u.x) + bv[j];
                float mem = 0.f, spk = 0.f;
                unsigned bits = 0;
#pragma unroll
                for (int t = 0; t < T_STEPS; t++) {
                    float cur = (t == 0) ? c0 : bv[j];
                    mem = fmaf(BETA_F, mem, cur) - spk;
                    bool s = (mem - THR_F) > 0.f;
                    spk = s ? THR_F : 0.f;
                    bits |= (unsigned)s << t;
                }
#pragma unroll
                for (int q = 0; q < 4; q++) {
#pragma unroll
                    for (int s2 = 0; s2 < 4; s2++)
                        pw[q] |= ((bits >> (q * 4 + s2)) & 1u) << (s2 * 8 + j);
                }
            }
        }
#pragma unroll
        for (int t = 0; t < T_STEPS; t++)
            pk[ty * 8 + i][t][tx] = (unsigned char)((pw[t >> 2] >> ((t & 3) * 8)) & 0xffu);
    }
    __syncthreads();

#pragma unroll
    for (int p = 0; p < 32; p++) {
        int q = tid + p * 256;
        int row = q >> 6;
        int rem = q & 63;
        int t = rem >> 2;
        int w = rem & 3;
        uchar4 b4 = *(const uchar4*)&pk[row][t][w * 4];
        unsigned word = (unsigned)b4.x | ((unsigned)b4.y << 8) |
                        ((unsigned)b4.z << 16) | ((unsigned)b4.w << 24);
        g_spk1[((size_t)(n0 + row) * 16 + t) * 16 + (h0 >> 5) + w] = word;
    }
}

// ---------------- K3: sparse layer-2, double-buffered lists + byte offsets --------
// Block 256 thr = 8 warps: 8 tokens x ALL 256 columns. One barrier per timestep:
// while warps accumulate step t from buffer t&1, builder threads expand step
// t+1's bitmasks into buffer (t+1)&1. Lists hold precomputed byte offsets
// (j*1024) so the hot loop is pure LDS -> LDG.128 -> FADD.
__global__ __launch_bounds__(256) void k_spike2(const float* __restrict__ b2) {
    __shared__ u32 offs[2][8][512];     // 32 KB
    __shared__ int counts[2][8];

    const int tid = threadIdx.x;
    const int n0 = blockIdx.x * 8;
    const int lane = tid & 31;
    const int wp = tid >> 5;
    const int i0 = (wp & 1) * 128 + lane * 4;
    const int rbase = (wp >> 1) * 2;
    const float4 b2v = *(const float4*)(b2 + i0);
    const char* __restrict__ w2base = (const char*)(g_W2T + i0);

    // builder role (threads 0..127): thread (r_, w_) expands word w_ of row r_
    const int r_ = tid >> 4;       // 0..7 for tid < 128
    const int w_ = tid & 15;
    const int sub = tid & 15;

    float m0[2], m1[2], m2[2], m3[2];
    float c0_[2], c1_[2], c2_[2], c3_[2];
#pragma unroll
    for (int r = 0; r < 2; r++) {
        m0[r] = m1[r] = m2[r] = m3[r] = 0.f;
        c0_[r] = c1_[r] = c2_[r] = c3_[r] = 0.f;
    }
    unsigned sp0 = 0, sp1 = 0, sp2 = 0, sp3 = 0;

    // prologue: build t = 0 into buffer 0
    if (tid < 128) {
        unsigned word = g_spk1[((size_t)(n0 + r_) * 16 + 0) * 16 + w_];
        int pc = __popc(word);
        int inc = pc;
#pragma unroll
        for (int off = 1; off < 16; off <<= 1) {
            int v = __shfl_up_sync(0xffffffffu, inc, off);
            if (sub >= off) inc += v;
        }
        int base = inc - pc;
        if (sub == 15) counts[0][r_] = inc;
        while (word) {
            int b = __ffs(word) - 1;
            word &= word - 1;
            offs[0][r_][base++] = ((u32)w_ << 15) + ((u32)b << 10);
        }
    }
    __syncthreads();

    for (int t = 0; t < T_STEPS; t++) {
        const int buf = t & 1;

        // build step t+1 into the other buffer (overlaps with accumulation below)
        if (tid < 128 && t + 1 < T_STEPS) {
            unsigned word = g_spk1[((size_t)(n0 + r_) * 16 + (t + 1)) * 16 + w_];
            int pc = __popc(word);
            int inc = pc;
#pragma unroll
            for (int off = 1; off < 16; off <<= 1) {
                int v = __shfl_up_sync(0xffffffffu, inc, off);
                if (sub >= off) inc += v;
            }
            int base = inc - pc;
            if (sub == 15) counts[buf ^ 1][r_] = inc;
            while (word) {
                int b = __ffs(word) - 1;
                word &= word - 1;
                offs[buf ^ 1][r_][base++] = ((u32)w_ << 15) + ((u32)b << 10);
            }
        }

        // accumulate step t
#pragma unroll
        for (int rr = 0; rr < 2; rr++) {
            const int r = rbase + rr;
            float cx = b2v.x, cy = b2v.y, cz = b2v.z, cw = b2v.w;
            const int ne = counts[buf][r];
            const u32* __restrict__ lst = offs[buf][r];
            int k = 0;
            for (; k + 8 <= ne; k += 8) {
                u32 o0 = lst[k + 0];
                u32 o1 = lst[k + 1];
                u32 o2 = lst[k + 2];
                u32 o3 = lst[k + 3];
                u32 o4 = lst[k + 4];
                u32 o5 = lst[k + 5];
                u32 o6 = lst[k + 6];
                u32 o7 = lst[k + 7];
                float4 v0 = __ldg((const float4*)(w2base + o0));
                float4 v1 = __ldg((const float4*)(w2base + o1));
                float4 v2 = __ldg((const float4*)(w2base + o2));
                float4 v3 = __ldg((const float4*)(w2base + o3));
                float4 v4 = __ldg((const float4*)(w2base + o4));
                float4 v5 = __ldg((const float4*)(w2base + o5));
                float4 v6 = __ldg((const float4*)(w2base + o6));
                float4 v7 = __ldg((const float4*)(w2base + o7));
                cx += ((v0.x + v1.x) + (v2.x + v3.x)) + ((v4.x + v5.x) + (v6.x + v7.x));
                cy += ((v0.y + v1.y) + (v2.y + v3.y)) + ((v4.y + v5.y) + (v6.y + v7.y));
                cz += ((v0.z + v1.z) + (v2.z + v3.z)) + ((v4.z + v5.z) + (v6.z + v7.z));
                cw += ((v0.w + v1.w) + (v2.w + v3.w)) + ((v4.w + v5.w) + (v6.w + v7.w));
            }
            for (; k < ne; k++) {
                float4 v = __ldg((const float4*)(w2base + lst[k]));
                cx += v.x; cy += v.y; cz += v.z; cw += v.w;
            }

            float n0v = fmaf(BETA_F, m0[rr], cx) - (((sp0 >> rr) & 1u) ? THR_F : 0.f);
            float n1v = fmaf(BETA_F, m1[rr], cy) - (((sp1 >> rr) & 1u) ? THR_F : 0.f);
            float n2v = fmaf(BETA_F, m2[rr], cz) - (((sp2 >> rr) & 1u) ? THR_F : 0.f);
            float n3v = fmaf(BETA_F, m3[rr], cw) - (((sp3 >> rr) & 1u) ? THR_F : 0.f);
            m0[rr] = n0v; m1[rr] = n1v; m2[rr] = n2v; m3[rr] = n3v;
            bool s0 = (n0v - THR_F) > 0.f;
            bool s1 = (n1v - THR_F) > 0.f;
            bool s2 = (n2v - THR_F) > 0.f;
            bool s3 = (n3v - THR_F) > 0.f;
            sp0 = (sp0 & ~(1u << rr)) | ((unsigned)s0 << rr);
            sp1 = (sp1 & ~(1u << rr)) | ((unsigned)s1 << rr);
            sp2 = (sp2 & ~(1u << rr)) | ((unsigned)s2 << rr);
            sp3 = (sp3 & ~(1u << rr)) | ((unsigned)s3 << rr);
            c0_[rr] += s0 ? 1.f : 0.f;
            c1_[rr] += s1 ? 1.f : 0.f;
            c2_[rr] += s2 ? 1.f : 0.f;
            c3_[rr] += s3 ? 1.f : 0.f;
        }
        __syncthreads();
    }

    // write bf16 cnt (integers 0..16: exact truncation to bf16)
#pragma unroll
    for (int rr = 0; rr < 2; rr++) {
        u32 p0 = (__float_as_uint(c0_[rr]) >> 16) | (__float_as_uint(c1_[rr]) & 0xffff0000u);
        u32 p1 = (__float_as_uint(c2_[rr]) >> 16) | (__float_as_uint(c3_[rr]) & 0xffff0000u);
        size_t base = ((size_t)(n0 + rbase + rr) * SU_DIM + i0) >> 1;
        g_sfb16[base]     = p0;
        g_sfb16[base + 1] = p1;
    }
}

// ---------------- K4: bf16-mma final GEMM + LN + ReLU (ping-pong, proven) ---------
#define KF_SMEM (33792 + 73728 + 1024)

__global__ __launch_bounds__(512, 1) void k_final(const float* __restrict__ ln_g,
                                                  const float* __restrict__ ln_b,
                                                  float* __restrict__ out) {
    extern __shared__ __align__(16) unsigned char smf[];
    u32*   As32 = (u32*)smf;
    u32*   bbuf = (u32*)(smf + 33792);
    float* red  = (float*)(smf + 33792 + 73728);

    const int tid  = threadIdx.x;
    const int warp = tid >> 5, lane = tid & 31;
    const int rg = warp >> 2, cg = warp & 3;
    const int g = lane >> 2, c = lane & 3;
    const int n0 = blockIdx.x * 64;

#pragma unroll
    for (int p = 0; p < 16; p++) {
        int e = tid + p * 512;
        int row = e >> 7, cw = e & 127;
        As32[row * 132 + cw] = g_sfb16[(size_t)(n0 + row) * 128 + cw];
    }
    {
        const uint4* src = (const uint4*)g_Wstg;
#pragma unroll
        for (int p = 0; p < 4; p++) {
            int q = tid + p * 512;
            uint4 v = __ldg(src + q);
            int h = (q >= 1024) ? 4608 : 0;
            int qq = q & 1023;
            u32* dst = bbuf + h + (qq >> 1) * 9 + (qq & 1) * 4;
            dst[0] = v.x; dst[1] = v.y; dst[2] = v.z; dst[3] = v.w;
        }
    }
    __syncthreads();

    float acc[16][4];
#pragma unroll
    for (int nt = 0; nt < 16; nt++)
#pragma unroll
        for (int q = 0; q < 4; q++) acc[nt][q] = 0.f;

    u32* cur = bbuf;
    u32* nxt = bbuf + 9216;

#pragma unroll 1
    for (int kc = 0; kc < 16; kc++) {
        uint4 pf0, pf1, pf2, pf3;
        if (kc < 15) {
            const uint4* src = (const uint4*)(g_Wstg + (kc + 1) * 8192);
            pf0 = __ldg(src + tid);
            pf1 = __ldg(src + tid + 512);
            pf2 = __ldg(src + tid + 1024);
            pf3 = __ldg(src + tid + 1536);
        }

        int ra = (rg * 16 + g) * 132 + kc * 8;
        int rb = ra + 8 * 132;
        u32 a0 = As32[ra + c];
        u32 a1 = As32[rb + c];
        u32 a2 = As32[ra + 4 + c];
        u32 a3 = As32[rb + 4 + c];
#pragma unroll
        for (int nt = 0; nt < 16; nt++) {
            int n = cg * 128 + nt * 8 + g;
            u32 b0 = cur[n * 9 + c];
            u32 b1 = cur[n * 9 + 4 + c];
            u32 e0 = cur[4608 + n * 9 + c];
            u32 e1 = cur[4608 + n * 9 + 4 + c];
            mma_bf16(acc[nt], a0, a1, a2, a3, b0, b1);
            mma_bf16(acc[nt], a0, a1, a2, a3, e0, e1);
        }

        if (kc < 15) {
            uint4 pf[4] = {pf0, pf1, pf2, pf3};
#pragma unroll
            for (int p = 0; p < 4; p++) {
                int q = tid + p * 512;
                int h = (q >= 1024) ? 4608 : 0;
                int qq = q & 1023;
                u32* dst = nxt + h + (qq >> 1) * 9 + (qq & 1) * 4;
                dst[0] = pf[p].x; dst[1] = pf[p].y; dst[2] = pf[p].z; dst[3] = pf[p].w;
            }
        }
        u32* tswap = cur; cur = nxt; nxt = tswap;
        __syncthreads();
    }

#pragma unroll
    for (int nt = 0; nt < 16; nt++) {
        float2 be = *(const float2*)(g_beff + cg * 128 + nt * 8 + c * 2);
        acc[nt][0] += be.x; acc[nt][1] += be.y;
        acc[nt][2] += be.x; acc[nt][3] += be.y;
    }

    const int rowA = rg * 16 + g, rowB = rowA + 8;

    float sA = 0.f, sB = 0.f;
#pragma unroll
    for (int nt = 0; nt < 16; nt++) {
        sA += acc[nt][0] + acc[nt][1];
        sB += acc[nt][2] + acc[nt][3];
    }
    sA += __shfl_xor_sync(0xffffffffu, sA, 1);
    sA += __shfl_xor_sync(0xffffffffu, sA, 2);
    sB += __shfl_xor_sync(0xffffffffu, sB, 1);
    sB += __shfl_xor_sync(0xffffffffu, sB, 2);
    if (c == 0) { red[rowA * 4 + cg] = sA; red[rowB * 4 + cg] = sB; }
    __syncthreads();
    float muA = (red[rowA * 4 + 0] + red[rowA * 4 + 1] +
                 red[rowA * 4 + 2] + red[rowA * 4 + 3]) * (1.f / 512.f);
    float muB = (red[rowB * 4 + 0] + red[rowB * 4 + 1] +
                 red[rowB * 4 + 2] + red[rowB * 4 + 3]) * (1.f / 512.f);
    __syncthreads();

    float qA = 0.f, qB = 0.f;
#pragma unroll
    for (int nt = 0; nt < 16; nt++) {
        float d0 = acc[nt][0] - muA, d1 = acc[nt][1] - muA;
        float d2 = acc[nt][2] - muB, d3 = acc[nt][3] - muB;
        qA = fmaf(d0, d0, qA); qA = fmaf(d1, d1, qA);
        qB = fmaf(d2, d2, qB); qB = fmaf(d3, d3, qB);
    }
    qA += __shfl_xor_sync(0xffffffffu, qA, 1);
    qA += __shfl_xor_sync(0xffffffffu, qA, 2);
    qB += __shfl_xor_sync(0xffffffffu, qB, 1);
    qB += __shfl_xor_sync(0xffffffffu, qB, 2);
    if (c == 0) { red[rowA * 4 + cg] = qA; red[rowB * 4 + cg] = qB; }
    __syncthreads();
    float vA = (red[rowA * 4 + 0] + red[rowA * 4 + 1] +
                red[rowA * 4 + 2] + red[rowA * 4 + 3]) * (1.f / 512.f);
    float vB = (red[rowB * 4 + 0] + red[rowB * 4 + 1] +
                red[rowB * 4 + 2] + red[rowB * 4 + 3]) * (1.f / 512.f);
    float rinvA = rsqrtf(vA + 1e-5f);
    float rinvB = rsqrtf(vB + 1e-5f);

#pragma unroll
    for (int nt = 0; nt < 16; nt++) {
        int col = cg * 128 + nt * 8 + c * 2;
        float2 gg = *(const float2*)(ln_g + col);
        float2 bb = *(const float2*)(ln_b + col);
        float2 oA, oB;
        oA.x = fmaxf(fmaf((acc[nt][0] - muA) * rinvA, gg.x, bb.x), 0.f);
        oA.y = fmaxf(fmaf((acc[nt][1] - muA) * rinvA, gg.y, bb.y), 0.f);
        oB.x = fmaxf(fmaf((acc[nt][2] - muB) * rinvB, gg.x, bb.x), 0.f);
        oB.y = fmaxf(fmaf((acc[nt][3] - muB) * rinvB, gg.y, bb.y), 0.f);
        *(float2*)(out + (size_t)(n0 + rowA) * 512 + col) = oA;
        *(float2*)(out + (size_t)(n0 + rowB) * 512 + col) = oB;
    }
}

// ---------------- launch ----------------
extern "C" void kernel_launch(void* const* d_in, const int* in_sizes, int n_in,
                              void* d_out, int out_size) {
    const float* x    = (const float*)d_in[0];
    const float* W1   = (const float*)d_in[1];
    const float* b1   = (const float*)d_in[2];
    const float* W2   = (const float*)d_in[3];
    const float* b2   = (const float*)d_in[4];
    const float* Wf   = (const float*)d_in[5];
    const float* bf   = (const float*)d_in[6];
    const float* Wfu  = (const float*)d_in[7];
    const float* bfu  = (const float*)d_in[8];
    const float* ln_g = (const float*)d_in[9];
    const float* ln_b = (const float*)d_in[10];
    float* out = (float*)d_out;

    cudaFuncSetAttribute(k_final, cudaFuncAttributeMaxDynamicSharedMemorySize, KF_SMEM);

    k_prep<<<1025, 256>>>(W2, Wfu, Wf, bf, bfu);
    k_gemm1<<<dim3(H1_DIM / K1_BN, N_ROWS / K1_BM), 256>>>(x, W1, b1);
    k_spike2<<<N_ROWS / 8, 256>>>(b2);
    k_final<<<N_ROWS / 64, 512, KF_SMEM>>>(ln_g, ln_b, out);
}

// round 17
// speedup vs baseline: 1.0178x; 1.0178x over previous
#include <cuda_runtime.h>
#include <cuda_bf16.h>

#define N_ROWS 8192
#define F_DIM  512
#define H1_DIM 512
#define SU_DIM 256
#define T_STEPS 16
#define BETA_F 0.95f
#define THR_F  1.0f

typedef unsigned int u32;
typedef unsigned long long u64;
typedef unsigned short u16;

// packed fp32x2 helpers (Blackwell native)
__device__ __forceinline__ u64 ffma2(u64 a, u64 b, u64 c) {
    u64 d;
    asm("fma.rn.f32x2 %0, %1, %2, %3;" : "=l"(d) : "l"(a), "l"(b), "l"(c));
    return d;
}
__device__ __forceinline__ u64 pack2(float x) {
    u64 d;
    asm("mov.b64 %0, {%1, %1};" : "=l"(d) : "f"(x));
    return d;
}
__device__ __forceinline__ float2 unpack2(u64 d) {
    float2 r;
    asm("mov.b64 {%0, %1}, %2;" : "=f"(r.x), "=f"(r.y) : "l"(d));
    return r;
}

// bf16 mma: D(16x8) += A(16x16) * B(16x8), fp32 accum
__device__ __forceinline__ void mma_bf16(float (&d)[4], u32 a0, u32 a1, u32 a2, u32 a3,
                                         u32 b0, u32 b1) {
    asm("mma.sync.aligned.m16n8k16.row.col.f32.bf16.bf16.f32 "
        "{%0,%1,%2,%3}, {%4,%5,%6,%7}, {%8,%9}, {%0,%1,%2,%3};"
        : "+f"(d[0]), "+f"(d[1]), "+f"(d[2]), "+f"(d[3])
        : "r"(a0), "r"(a1), "r"(a2), "r"(a3), "r"(b0), "r"(b1));
}

// ---------------- scratch (static device globals; no allocations) ----------------
__device__ unsigned g_spk1[N_ROWS * T_STEPS * (H1_DIM / 32)];  // 8 MB
__device__ __align__(16) u32 g_sfb16[N_ROWS * SU_DIM / 2];     // bf16 cnt pairs
__device__ float g_W2T[H1_DIM * SU_DIM];                       // [j][i]
__device__ __align__(16) u32 g_Wstg[16 * 8192];                // k_final staged W
__device__ float g_beff[F_DIM];

// ---------------- fused prep ----------------
__global__ __launch_bounds__(256) void k_prep(const float* __restrict__ W2,
                                              const float* __restrict__ Wfu,
                                              const float* __restrict__ Wf,
                                              const float* __restrict__ bf,
                                              const float* __restrict__ bfu) {
    int bid = blockIdx.x;
    if (bid < 512) {
        __shared__ float wrow[256];
        int f = bid;
        int i = threadIdx.x;
        wrow[i] = Wfu[f * 512 + i];
        __syncthreads();
        float acc = Wfu[f * 512 + 256 + i];
#pragma unroll 4
        for (int l = 0; l < 256; l++)
            acc = fmaf(wrow[l], Wf[l * 256 + i], acc);
        float w = acc * (1.f / 16.f);
        __nv_bfloat16 h = __float2bfloat16(w);
        float hf = __bfloat162float(h);
        __nv_bfloat16 lo = __float2bfloat16(w - hf);
        u16* ws = (u16*)g_Wstg;
        int kc = i >> 4, r = i & 15;
        ws[kc * 16384 + f * 16 + r]        = __bfloat16_as_ushort(h);
        ws[kc * 16384 + 8192 + f * 16 + r] = __bfloat16_as_ushort(lo);
    } else if (bid < 1024) {
        int idx = (bid - 512) * 256 + threadIdx.x;
        int i = idx >> 9;
        int j = idx & 511;
        g_W2T[j * SU_DIM + i] = W2[idx];
    } else {
#pragma unroll
        for (int p = 0; p < 2; p++) {
            int f = threadIdx.x + p * 256;
            float acc = bfu[f];
#pragma unroll 4
            for (int l = 0; l < 256; l++)
                acc = fmaf(Wfu[f * 512 + l], bf[l], acc);
            g_beff[f] = acc;
        }
    }
}

// ---------------- K1: cur0 = X @ W1^T + b1, FUSED spike recurrence, f32x2 ----------
// Double-buffered smem mainloop: ONE barrier per 16-k chunk (32 total, was 64);
// next chunk's STS overlaps other warps' compute instead of sitting between
// two barriers. Numerics identical.
#define K1_BM 128
#define K1_BN 128
#define K1_BK 16
#define K1_LDS 136
#define K1_BUF (2 * K1_BK * K1_LDS)   // floats per buffer (As+Bs) = 4352

__global__ __launch_bounds__(256, 2) void k_gemm1(const float* __restrict__ X,
                                                  const float* __restrict__ W1,
                                                  const float* __restrict__ b1) {
    __shared__ __align__(16) unsigned char sm[2 * K1_BUF * 4];  // 34816 B
    float* smf = (float*)sm;
    unsigned char (*pk)[16][16] = (unsigned char (*)[16][16])sm;  // epilogue union

    const int n0 = blockIdx.y * K1_BM;
    const int h0 = blockIdx.x * K1_BN;
    const int tid = threadIdx.x;
    const int ty = tid >> 4;
    const int tx = tid & 15;

    const int lrow0 = tid >> 2;
    const int lkq0  = tid & 3;
    const int lrow1 = (tid + 256) >> 2;
    const int lkq1  = (tid + 256) & 3;

    float4 pa0, pa1, pb0, pb1;
    {
        pa0 = *(const float4*)(X  + (size_t)(n0 + lrow0) * 512 + lkq0 * 4);
        pb0 = *(const float4*)(W1 + (size_t)(h0 + lrow0) * 512 + lkq0 * 4);
        pa1 = *(const float4*)(X  + (size_t)(n0 + lrow1) * 512 + lkq1 * 4);
        pb1 = *(const float4*)(W1 + (size_t)(h0 + lrow1) * 512 + lkq1 * 4);
    }

    u64 accp[8][4];
#pragma unroll
    for (int i = 0; i < 8; i++)
#pragma unroll
        for (int jp = 0; jp < 4; jp++) accp[i][jp] = 0ull;

    // store chunk 0 into buffer 0
    {
        float* A = smf;
        float* B = smf + K1_BK * K1_LDS;
        A[(lkq0 * 4 + 0) * K1_LDS + lrow0] = pa0.x;
        A[(lkq0 * 4 + 1) * K1_LDS + lrow0] = pa0.y;
        A[(lkq0 * 4 + 2) * K1_LDS + lrow0] = pa0.z;
        A[(lkq0 * 4 + 3) * K1_LDS + lrow0] = pa0.w;
        B[(lkq0 * 4 + 0) * K1_LDS + lrow0] = pb0.x;
        B[(lkq0 * 4 + 1) * K1_LDS + lrow0] = pb0.y;
        B[(lkq0 * 4 + 2) * K1_LDS + lrow0] = pb0.z;
        B[(lkq0 * 4 + 3) * K1_LDS + lrow0] = pb0.w;
        A[(lkq1 * 4 + 0) * K1_LDS + lrow1] = pa1.x;
        A[(lkq1 * 4 + 1) * K1_LDS + lrow1] = pa1.y;
        A[(lkq1 * 4 + 2) * K1_LDS + lrow1] = pa1.z;
        A[(lkq1 * 4 + 3) * K1_LDS + lrow1] = pa1.w;
        B[(lkq1 * 4 + 0) * K1_LDS + lrow1] = pb1.x;
        B[(lkq1 * 4 + 1) * K1_LDS + lrow1] = pb1.y;
        B[(lkq1 * 4 + 2) * K1_LDS + lrow1] = pb1.z;
        B[(lkq1 * 4 + 3) * K1_LDS + lrow1] = pb1.w;
    }
    __syncthreads();

#pragma unroll 1
    for (int it = 0; it < 32; it++) {
        const int cb = it & 1;
        const float* A = smf + cb * K1_BUF;
        const float* B = A + K1_BK * K1_LDS;

        if (it < 31) {
            int kn = (it + 1) * K1_BK;
            pa0 = *(const float4*)(X  + (size_t)(n0 + lrow0) * 512 + kn + lkq0 * 4);
            pb0 = *(const float4*)(W1 + (size_t)(h0 + lrow0) * 512 + kn + lkq0 * 4);
            pa1 = *(const float4*)(X  + (size_t)(n0 + lrow1) * 512 + kn + lkq1 * 4);
            pb1 = *(const float4*)(W1 + (size_t)(h0 + lrow1) * 512 + kn + lkq1 * 4);
        }

#pragma unroll
        for (int k = 0; k < K1_BK; k++) {
            float a[8];
            *(float4*)(a)     = *(const float4*)&A[k * K1_LDS + ty * 8];
            *(float4*)(a + 4) = *(const float4*)&A[k * K1_LDS + ty * 8 + 4];
            ulonglong2 t0 = *(const ulonglong2*)&B[k * K1_LDS + tx * 8];
            ulonglong2 t1 = *(const ulonglong2*)&B[k * K1_LDS + tx * 8 + 4];
            u64 b2[4] = {t0.x, t0.y, t1.x, t1.y};
#pragma unroll
            for (int i = 0; i < 8; i++) {
                u64 a2 = pack2(a[i]);
#pragma unroll
                for (int jp = 0; jp < 4; jp++)
                    accp[i][jp] = ffma2(a2, b2[jp], accp[i][jp]);
            }
        }

        if (it < 31) {
            float* An = smf + (cb ^ 1) * K1_BUF;
            float* Bn = An + K1_BK * K1_LDS;
            An[(lkq0 * 4 + 0) * K1_LDS + lrow0] = pa0.x;
            An[(lkq0 * 4 + 1) * K1_LDS + lrow0] = pa0.y;
            An[(lkq0 * 4 + 2) * K1_LDS + lrow0] = pa0.z;
            An[(lkq0 * 4 + 3) * K1_LDS + lrow0] = pa0.w;
            Bn[(lkq0 * 4 + 0) * K1_LDS + lrow0] = pb0.x;
            Bn[(lkq0 * 4 + 1) * K1_LDS + lrow0] = pb0.y;
            Bn[(lkq0 * 4 + 2) * K1_LDS + lrow0] = pb0.z;
            Bn[(lkq0 * 4 + 3) * K1_LDS + lrow0] = pb0.w;
            An[(lkq1 * 4 + 0) * K1_LDS + lrow1] = pa1.x;
            An[(lkq1 * 4 + 1) * K1_LDS + lrow1] = pa1.y;
            An[(lkq1 * 4 + 2) * K1_LDS + lrow1] = pa1.z;
            An[(lkq1 * 4 + 3) * K1_LDS + lrow1] = pa1.w;
            Bn[(lkq1 * 4 + 0) * K1_LDS + lrow1] = pb1.x;
            Bn[(lkq1 * 4 + 1) * K1_LDS + lrow1] = pb1.y;
            Bn[(lkq1 * 4 + 2) * K1_LDS + lrow1] = pb1.z;
            Bn[(lkq1 * 4 + 3) * K1_LDS + lrow1] = pb1.w;
        }
        __syncthreads();
    }

    float bv[8];
#pragma unroll
    for (int j = 0; j < 8; j++) bv[j] = b1[h0 + tx * 8 + j];

#pragma unroll
    for (int i = 0; i < 8; i++) {
        unsigned pw[4] = {0u, 0u, 0u, 0u};
#pragma unroll
        for (int jp = 0; jp < 4; jp++) {
            float2 u = unpack2(accp[i][jp]);
#pragma unroll
            for (int h = 0; h < 2; h++) {
                int j = jp * 2 + h;
                float c0 = (h ? u.y : u.x) + bv[j];
                float mem = 0.f, spk = 0.f;
                unsigned bits = 0;
#pragma unroll
                for (int t = 0; t < T_STEPS; t++) {
                    float cur = (t == 0) ? c0 : bv[j];
                    mem = fmaf(BETA_F, mem, cur) - spk;
                    bool s = (mem - THR_F) > 0.f;
                    spk = s ? THR_F : 0.f;
                    bits |= (unsigned)s << t;
                }
#pragma unroll
                for (int q = 0; q < 4; q++) {
#pragma unroll
                    for (int s2 = 0; s2 < 4; s2++)
                        pw[q] |= ((bits >> (q * 4 + s2)) & 1u) << (s2 * 8 + j);
                }
            }
        }
#pragma unroll
        for (int t = 0; t < T_STEPS; t++)
            pk[ty * 8 + i][t][tx] = (unsigned char)((pw[t >> 2] >> ((t & 3) * 8)) & 0xffu);
    }
    __syncthreads();

#pragma unroll
    for (int p = 0; p < 32; p++) {
        int q = tid + p * 256;
        int row = q >> 6;
        int rem = q & 63;
        int t = rem >> 2;
        int w = rem & 3;
        uchar4 b4 = *(const uchar4*)&pk[row][t][w * 4];
        unsigned word = (unsigned)b4.x | ((unsigned)b4.y << 8) |
                        ((unsigned)b4.z << 16) | ((unsigned)b4.w << 24);
        g_spk1[((size_t)(n0 + row) * 16 + t) * 16 + (h0 >> 5) + w] = word;
    }
}

// ---------------- K3: sparse spike-driven layer-2, lists built ONCE per token -----
// (r15 proven version: 8 tokens x all 256 cols, float4 per warp-half)
__global__ __launch_bounds__(256) void k_spike2(const float* __restrict__ b2) {
    __shared__ unsigned short lists[8][512];
    __shared__ int counts[8];

    const int tid = threadIdx.x;
    const int n0 = blockIdx.x * 8;
    const int lane = tid & 31;
    const int wp = tid >> 5;
    const int i0 = (wp & 1) * 128 + lane * 4;
    const int rbase = (wp >> 1) * 2;
    const float4 b2v = *(const float4*)(b2 + i0);
    const float* __restrict__ w2col = g_W2T + i0;

    const int r_ = tid >> 4;
    const int w_ = tid & 15;
    const int sub = tid & 15;

    float m0[2], m1[2], m2[2], m3[2];
    float c0_[2], c1_[2], c2_[2], c3_[2];
#pragma unroll
    for (int r = 0; r < 2; r++) {
        m0[r] = m1[r] = m2[r] = m3[r] = 0.f;
        c0_[r] = c1_[r] = c2_[r] = c3_[r] = 0.f;
    }
    unsigned sp0 = 0, sp1 = 0, sp2 = 0, sp3 = 0;

    for (int t = 0; t < T_STEPS; t++) {
        __syncthreads();

        if (tid < 128) {
            unsigned word = g_spk1[((size_t)(n0 + r_) * 16 + t) * 16 + w_];
            int pc = __popc(word);
            int inc = pc;
#pragma unroll
            for (int off = 1; off < 16; off <<= 1) {
                int v = __shfl_up_sync(0xffffffffu, inc, off);
                if (sub >= off) inc += v;
            }
            int base = inc - pc;
            if (sub == 15) counts[r_] = inc;
            while (word) {
                int b = __ffs(word) - 1;
                word &= word - 1;
                lists[r_][base++] = (unsigned short)(w_ * 32 + b);
            }
        }
        __syncthreads();

#pragma unroll
        for (int rr = 0; rr < 2; rr++) {
            const int r = rbase + rr;
            float cx = b2v.x, cy = b2v.y, cz = b2v.z, cw = b2v.w;
            const int ne = counts[r];
            int k = 0;
            for (; k + 8 <= ne; k += 8) {
                int j0 = lists[r][k + 0];
                int j1 = lists[r][k + 1];
                int j2 = lists[r][k + 2];
                int j3 = lists[r][k + 3];
                int j4 = lists[r][k + 4];
                int j5 = lists[r][k + 5];
                int j6 = lists[r][k + 6];
                int j7 = lists[r][k + 7];
                float4 v0 = __ldg((const float4*)(w2col + j0 * SU_DIM));
                float4 v1 = __ldg((const float4*)(w2col + j1 * SU_DIM));
                float4 v2 = __ldg((const float4*)(w2col + j2 * SU_DIM));
                float4 v3 = __ldg((const float4*)(w2col + j3 * SU_DIM));
                float4 v4 = __ldg((const float4*)(w2col + j4 * SU_DIM));
                float4 v5 = __ldg((const float4*)(w2col + j5 * SU_DIM));
                float4 v6 = __ldg((const float4*)(w2col + j6 * SU_DIM));
                float4 v7 = __ldg((const float4*)(w2col + j7 * SU_DIM));
                cx += ((v0.x + v1.x) + (v2.x + v3.x)) + ((v4.x + v5.x) + (v6.x + v7.x));
                cy += ((v0.y + v1.y) + (v2.y + v3.y)) + ((v4.y + v5.y) + (v6.y + v7.y));
                cz += ((v0.z + v1.z) + (v2.z + v3.z)) + ((v4.z + v5.z) + (v6.z + v7.z));
                cw += ((v0.w + v1.w) + (v2.w + v3.w)) + ((v4.w + v5.w) + (v6.w + v7.w));
            }
            for (; k < ne; k++) {
                float4 v = __ldg((const float4*)(w2col + lists[r][k] * SU_DIM));
                cx += v.x; cy += v.y; cz += v.z; cw += v.w;
            }

            float n0v = fmaf(BETA_F, m0[rr], cx) - (((sp0 >> rr) & 1u) ? THR_F : 0.f);
            float n1v = fmaf(BETA_F, m1[rr], cy) - (((sp1 >> rr) & 1u) ? THR_F : 0.f);
            float n2v = fmaf(BETA_F, m2[rr], cz) - (((sp2 >> rr) & 1u) ? THR_F : 0.f);
            float n3v = fmaf(BETA_F, m3[rr], cw) - (((sp3 >> rr) & 1u) ? THR_F : 0.f);
            m0[rr] = n0v; m1[rr] = n1v; m2[rr] = n2v; m3[rr] = n3v;
            bool s0 = (n0v - THR_F) > 0.f;
            bool s1 = (n1v - THR_F) > 0.f;
            bool s2 = (n2v - THR_F) > 0.f;
            bool s3 = (n3v - THR_F) > 0.f;
            sp0 = (sp0 & ~(1u << rr)) | ((unsigned)s0 << rr);
            sp1 = (sp1 & ~(1u << rr)) | ((unsigned)s1 << rr);
            sp2 = (sp2 & ~(1u << rr)) | ((unsigned)s2 << rr);
            sp3 = (sp3 & ~(1u << rr)) | ((unsigned)s3 << rr);
            c0_[rr] += s0 ? 1.f : 0.f;
            c1_[rr] += s1 ? 1.f : 0.f;
            c2_[rr] += s2 ? 1.f : 0.f;
            c3_[rr] += s3 ? 1.f : 0.f;
        }
    }

    // write bf16 cnt (integers 0..16: exact truncation to bf16)
#pragma unroll
    for (int rr = 0; rr < 2; rr++) {
        u32 p0 = (__float_as_uint(c0_[rr]) >> 16) | (__float_as_uint(c1_[rr]) & 0xffff0000u);
        u32 p1 = (__float_as_uint(c2_[rr]) >> 16) | (__float_as_uint(c3_[rr]) & 0xffff0000u);
        size_t base = ((size_t)(n0 + rbase + rr) * SU_DIM + i0) >> 1;
        g_sfb16[base]     = p0;
        g_sfb16[base + 1] = p1;
    }
}

// ---------------- K4: bf16-mma final GEMM + LN + ReLU (ping-pong, proven) ---------
#define KF_SMEM (33792 + 73728 + 1024)

__global__ __launch_bounds__(512, 1) void k_final(const float* __restrict__ ln_g,
                                                  const float* __restrict__ ln_b,
                                                  float* __restrict__ out) {
    extern __shared__ __align__(16) unsigned char smf2[];
    u32*   As32 = (u32*)smf2;
    u32*   bbuf = (u32*)(smf2 + 33792);
    float* red  = (float*)(smf2 + 33792 + 73728);

    const int tid  = threadIdx.x;
    const int warp = tid >> 5, lane = tid & 31;
    const int rg = warp >> 2, cg = warp & 3;
    const int g = lane >> 2, c = lane & 3;
    const int n0 = blockIdx.x * 64;

#pragma unroll
    for (int p = 0; p < 16; p++) {
        int e = tid + p * 512;
        int row = e >> 7, cw = e & 127;
        As32[row * 132 + cw] = g_sfb16[(size_t)(n0 + row) * 128 + cw];
    }
    {
        const uint4* src = (const uint4*)g_Wstg;
#pragma unroll
        for (int p = 0; p < 4; p++) {
            int q = tid + p * 512;
            uint4 v = __ldg(src + q);
            int h = (q >= 1024) ? 4608 : 0;
            int qq = q & 1023;
            u32* dst = bbuf + h + (qq >> 1) * 9 + (qq & 1) * 4;
            dst[0] = v.x; dst[1] = v.y; dst[2] = v.z; dst[3] = v.w;
        }
    }
    __syncthreads();

    float acc[16][4];
#pragma unroll
    for (int nt = 0; nt < 16; nt++)
#pragma unroll
        for (int q = 0; q < 4; q++) acc[nt][q] = 0.f;

    u32* cur = bbuf;
    u32* nxt = bbuf + 9216;

#pragma unroll 1
    for (int kc = 0; kc < 16; kc++) {
        uint4 pf0, pf1, pf2, pf3;
        if (kc < 15) {
            const uint4* src = (const uint4*)(g_Wstg + (kc + 1) * 8192);
            pf0 = __ldg(src + tid);
            pf1 = __ldg(src + tid + 512);
            pf2 = __ldg(src + tid + 1024);
            pf3 = __ldg(src + tid + 1536);
        }

        int ra = (rg * 16 + g) * 132 + kc * 8;
        int rb = ra + 8 * 132;
        u32 a0 = As32[ra + c];
        u32 a1 = As32[rb + c];
        u32 a2 = As32[ra + 4 + c];
        u32 a3 = As32[rb + 4 + c];
#pragma unroll
        for (int nt = 0; nt < 16; nt++) {
            int n = cg * 128 + nt * 8 + g;
            u32 b0 = cur[n * 9 + c];
            u32 b1 = cur[n * 9 + 4 + c];
            u32 e0 = cur[4608 + n * 9 + c];
            u32 e1 = cur[4608 + n * 9 + 4 + c];
            mma_bf16(acc[nt], a0, a1, a2, a3, b0, b1);
            mma_bf16(acc[nt], a0, a1, a2, a3, e0, e1);
        }

        if (kc < 15) {
            uint4 pf[4] = {pf0, pf1, pf2, pf3};
#pragma unroll
            for (int p = 0; p < 4; p++) {
                int q = tid + p * 512;
                int h = (q >= 1024) ? 4608 : 0;
                int qq = q & 1023;
                u32* dst = nxt + h + (qq >> 1) * 9 + (qq & 1) * 4;
                dst[0] = pf[p].x; dst[1] = pf[p].y; dst[2] = pf[p].z; dst[3] = pf[p].w;
            }
        }
        u32* tswap = cur; cur = nxt; nxt = tswap;
        __syncthreads();
    }

#pragma unroll
    for (int nt = 0; nt < 16; nt++) {
        float2 be = *(const float2*)(g_beff + cg * 128 + nt * 8 + c * 2);
        acc[nt][0] += be.x; acc[nt][1] += be.y;
        acc[nt][2] += be.x; acc[nt][3] += be.y;
    }

    const int rowA = rg * 16 + g, rowB = rowA + 8;

    float sA = 0.f, sB = 0.f;
#pragma unroll
    for (int nt = 0; nt < 16; nt++) {
        sA += acc[nt][0] + acc[nt][1];
        sB += acc[nt][2] + acc[nt][3];
    }
    sA += __shfl_xor_sync(0xffffffffu, sA, 1);
    sA += __shfl_xor_sync(0xffffffffu, sA, 2);
    sB += __shfl_xor_sync(0xffffffffu, sB, 1);
    sB += __shfl_xor_sync(0xffffffffu, sB, 2);
    if (c == 0) { red[rowA * 4 + cg] = sA; red[rowB * 4 + cg] = sB; }
    __syncthreads();
    float muA = (red[rowA * 4 + 0] + red[rowA * 4 + 1] +
                 red[rowA * 4 + 2] + red[rowA * 4 + 3]) * (1.f / 512.f);
    float muB = (red[rowB * 4 + 0] + red[rowB * 4 + 1] +
                 red[rowB * 4 + 2] + red[rowB * 4 + 3]) * (1.f / 512.f);
    __syncthreads();

    float qA = 0.f, qB = 0.f;
#pragma unroll
    for (int nt = 0; nt < 16; nt++) {
        float d0 = acc[nt][0] - muA, d1 = acc[nt][1] - muA;
        float d2 = acc[nt][2] - muB, d3 = acc[nt][3] - muB;
        qA = fmaf(d0, d0, qA); qA = fmaf(d1, d1, qA);
        qB = fmaf(d2, d2, qB); qB = fmaf(d3, d3, qB);
    }
    qA += __shfl_xor_sync(0xffffffffu, qA, 1);
    qA += __shfl_xor_sync(0xffffffffu, qA, 2);
    qB += __shfl_xor_sync(0xffffffffu, qB, 1);
    qB += __shfl_xor_sync(0xffffffffu, qB, 2);
    if (c == 0) { red[rowA * 4 + cg] = qA; red[rowB * 4 + cg] = qB; }
    __syncthreads();
    float vA = (red[rowA * 4 + 0] + red[rowA * 4 + 1] +
                red[rowA * 4 + 2] + red[rowA * 4 + 3]) * (1.f / 512.f);
    float vB = (red[rowB * 4 + 0] + red[rowB * 4 + 1] +
                red[rowB * 4 + 2] + red[rowB * 4 + 3]) * (1.f / 512.f);
    float rinvA = rsqrtf(vA + 1e-5f);
    float rinvB = rsqrtf(vB + 1e-5f);

#pragma unroll
    for (int nt = 0; nt < 16; nt++) {
        int col = cg * 128 + nt * 8 + c * 2;
        float2 gg = *(const float2*)(ln_g + col);
        float2 bb = *(const float2*)(ln_b + col);
        float2 oA, oB;
        oA.x = fmaxf(fmaf((acc[nt][0] - muA) * rinvA, gg.x, bb.x), 0.f);
        oA.y = fmaxf(fmaf((acc[nt][1] - muA) * rinvA, gg.y, bb.y), 0.f);
        oB.x = fmaxf(fmaf((acc[nt][2] - muB) * rinvB, gg.x, bb.x), 0.f);
        oB.y = fmaxf(fmaf((acc[nt][3] - muB) * rinvB, gg.y, bb.y), 0.f);
        *(float2*)(out + (size_t)(n0 + rowA) * 512 + col) = oA;
        *(float2*)(out + (size_t)(n0 + rowB) * 512 + col) = oB;
    }
}

// ---------------- launch ----------------
extern "C" void kernel_launch(void* const* d_in, const int* in_sizes, int n_in,
                              void* d_out, int out_size) {
    const float* x    = (const float*)d_in[0];
    const float* W1   = (const float*)d_in[1];
    const float* b1   = (const float*)d_in[2];
    const float* W2   = (const float*)d_in[3];
    const float* b2   = (const float*)d_in[4];
    const float* Wf   = (const float*)d_in[5];
    const float* bf   = (const float*)d_in[6];
    const float* Wfu  = (const float*)d_in[7];
    const float* bfu  = (const float*)d_in[8];
    const float* ln_g = (const float*)d_in[9];
    const float* ln_b = (const float*)d_in[10];
    float* out = (float*)d_out;

    cudaFuncSetAttribute(k_final, cudaFuncAttributeMaxDynamicSharedMemorySize, KF_SMEM);

    k_prep<<<1025, 256>>>(W2, Wfu, Wf, bf, bfu);
    k_gemm1<<<dim3(H1_DIM / K1_BN, N_ROWS / K1_BM), 256>>>(x, W1, b1);
    k_spike2<<<N_ROWS / 8, 256>>>(b2);
    k_final<<<N_ROWS / 64, 512, KF_SMEM>>>(ln_g, ln_b, out);
}